// round 3
// baseline (speedup 1.0000x reference)
#include <cuda_runtime.h>
#include <math_constants.h>
#include <mma.h>

using namespace nvcuda;

#define N_PTS   92160
#define D_DIM   192
#define BD_DIM  256
#define H_HEADS 8
#define FF_DIM  768
#define S_SETS  2560
#define L_LEN   36
#define M_BOX   256
#define HD_DIM  24

// ---------------- scratch (static device globals; no allocation) ----------------
__device__ float g_q[N_PTS * D_DIM];
__device__ float g_ctx[N_PTS * D_DIM];
__device__ float g_proj[N_PTS * D_DIM];
__device__ float g_x[N_PTS * D_DIM];
__device__ float g_y[N_PTS * D_DIM];
__device__ float g_h[(size_t)N_PTS * FF_DIM];
__device__ float g_k[M_BOX * D_DIM];
__device__ float g_v[M_BOX * D_DIM];
__device__ int   g_fp[N_PTS];

// ================= tf32 tensor-core GEMM: C = A @ W^T + bias =================
// A: (Mrows, K) fp32 row-major, W: (Dout, K) fp32 row-major, C: (Mrows, Dout)
// CTA tile 128 x 64, BK = 16, 256 threads = 8 warps (4 x 2), warp tile 32 x 32.
#define TBM 128
#define TBN 64
#define TBK 16
#define KPAD 24           // smem row stride (multiple of 8 for wmma ldm)

template<bool RELU>
__global__ __launch_bounds__(256)
void wmma_gemm(const float* __restrict__ A, const float* __restrict__ W,
               const float* __restrict__ bias, float* __restrict__ C,
               int K, int Dout)
{
    extern __shared__ float sm[];
    float* As = sm;                    // [128][KPAD]
    float* Ws = sm + TBM * KPAD;       // [64][KPAD]
    float* Cs = sm;                    // alias, [128][64] epilogue

    const int tid = threadIdx.x;
    const int wid = tid >> 5;
    const int warp_m = wid & 3;        // 0..3
    const int warp_n = wid >> 2;       // 0..1
    const int m0 = blockIdx.y * TBM;
    const int n0 = blockIdx.x * TBN;

    const int ar  = tid >> 2;          // 0..63
    const int ac4 = (tid & 3) << 2;    // 0,4,8,12

    const float* Ap0 = A + (size_t)(m0 + ar)      * K + ac4;
    const float* Ap1 = A + (size_t)(m0 + ar + 64) * K + ac4;
    const float* Wp  = W + (size_t)(n0 + ar)      * K + ac4;

    const int nT = K / TBK;

    float4 pa0 = *(const float4*)Ap0;
    float4 pa1 = *(const float4*)Ap1;
    float4 pw  = *(const float4*)Wp;

    wmma::fragment<wmma::accumulator, 16, 16, 8, float> acc[2][2];
    #pragma unroll
    for (int i = 0; i < 2; i++)
        #pragma unroll
        for (int j = 0; j < 2; j++) wmma::fill_fragment(acc[i][j], 0.0f);

    for (int t = 0; t < nT; ++t) {
        *(float4*)(As + (size_t)ar        * KPAD + ac4) = pa0;
        *(float4*)(As + (size_t)(ar + 64) * KPAD + ac4) = pa1;
        *(float4*)(Ws + (size_t)ar        * KPAD + ac4) = pw;
        __syncthreads();

        if (t + 1 < nT) {
            const int off = (t + 1) * TBK;
            pa0 = *(const float4*)(Ap0 + off);
            pa1 = *(const float4*)(Ap1 + off);
            pw  = *(const float4*)(Wp  + off);
        }

        #pragma unroll
        for (int kk = 0; kk < 2; ++kk) {
            wmma::fragment<wmma::matrix_a, 16, 16, 8, wmma::precision::tf32, wmma::row_major> af[2];
            wmma::fragment<wmma::matrix_b, 16, 16, 8, wmma::precision::tf32, wmma::col_major> bf[2];
            #pragma unroll
            for (int i = 0; i < 2; i++) {
                wmma::load_matrix_sync(af[i], As + (size_t)(warp_m * 32 + i * 16) * KPAD + kk * 8, KPAD);
                #pragma unroll
                for (int e = 0; e < af[i].num_elements; e++)
                    af[i].x[e] = wmma::__float_to_tf32(af[i].x[e]);
            }
            #pragma unroll
            for (int j = 0; j < 2; j++) {
                wmma::load_matrix_sync(bf[j], Ws + (size_t)(warp_n * 32 + j * 16) * KPAD + kk * 8, KPAD);
                #pragma unroll
                for (int e = 0; e < bf[j].num_elements; e++)
                    bf[j].x[e] = wmma::__float_to_tf32(bf[j].x[e]);
            }
            #pragma unroll
            for (int i = 0; i < 2; i++)
                #pragma unroll
                for (int j = 0; j < 2; j++)
                    wmma::mma_sync(acc[i][j], af[i], bf[j], acc[i][j]);
        }
        __syncthreads();
    }

    // epilogue: park accumulators in smem (aliases As/Ws), then bias(+relu) to global
    #pragma unroll
    for (int i = 0; i < 2; i++)
        #pragma unroll
        for (int j = 0; j < 2; j++)
            wmma::store_matrix_sync(Cs + (size_t)(warp_m * 32 + i * 16) * TBN + warp_n * 32 + j * 16,
                                    acc[i][j], TBN, wmma::mem_row_major);
    __syncthreads();

    #pragma unroll
    for (int e = 0; e < 8; ++e) {
        const int q  = tid + e * 256;            // quad index, 2048 total
        const int r  = q >> 4;                   // 0..127
        const int c4 = (q & 15) << 2;            // 0..60
        float4 v = *(float4*)(Cs + (size_t)r * TBN + c4);
        v.x += bias[n0 + c4 + 0];
        v.y += bias[n0 + c4 + 1];
        v.z += bias[n0 + c4 + 2];
        v.w += bias[n0 + c4 + 3];
        if (RELU) {
            v.x = fmaxf(v.x, 0.f); v.y = fmaxf(v.y, 0.f);
            v.z = fmaxf(v.z, 0.f); v.w = fmaxf(v.w, 0.f);
        }
        *(float4*)(C + (size_t)(m0 + r) * Dout + n0 + c4) = v;
    }
}

#define WMMA_SMEM (TBM * TBN * 4)   // 32 KB (>= stage size 18.4 KB)

// ---------------- small SIMT GEMM for K/V projections ----------------
#define BM 128
#define BN 64
#define BK 16

template<bool RELU, bool ADD2>
__global__ __launch_bounds__(256, 2)
void gemm_kernel(const float* __restrict__ A, const float* __restrict__ A2,
                 const float* __restrict__ W, const float* __restrict__ bias,
                 float* __restrict__ C, int K, int Dout)
{
    __shared__ float As[BK][BM + 4];
    __shared__ float Ws[BK][BN + 4];

    const int tid = threadIdx.x;
    const int tx = tid & 15;
    const int ty = tid >> 4;
    const int m0 = blockIdx.y * BM;
    const int n0 = blockIdx.x * BN;

    const int ar = tid >> 2;
    const int ac = (tid & 3) << 2;

    const float* Ap0  = A  + (size_t)(m0 + ar)      * K + ac;
    const float* Ap1  = A  + (size_t)(m0 + ar + 64) * K + ac;
    const float* A2p0 = ADD2 ? (A2 + (size_t)(m0 + ar)      * K + ac) : nullptr;
    const float* A2p1 = ADD2 ? (A2 + (size_t)(m0 + ar + 64) * K + ac) : nullptr;
    const float* Wp   = W  + (size_t)(n0 + ar)      * K + ac;

    const int nT = K / BK;

    float4 pa0 = *(const float4*)(Ap0);
    float4 pa1 = *(const float4*)(Ap1);
    float4 pw  = *(const float4*)(Wp);
    if (ADD2) {
        float4 q0 = *(const float4*)(A2p0);
        float4 q1 = *(const float4*)(A2p1);
        pa0.x += q0.x; pa0.y += q0.y; pa0.z += q0.z; pa0.w += q0.w;
        pa1.x += q1.x; pa1.y += q1.y; pa1.z += q1.z; pa1.w += q1.w;
    }

    float acc[8][4];
    #pragma unroll
    for (int i = 0; i < 8; i++)
        #pragma unroll
        for (int j = 0; j < 4; j++) acc[i][j] = 0.f;

    for (int t = 0; t < nT; ++t) {
        As[ac+0][ar]    = pa0.x; As[ac+1][ar]    = pa0.y;
        As[ac+2][ar]    = pa0.z; As[ac+3][ar]    = pa0.w;
        As[ac+0][ar+64] = pa1.x; As[ac+1][ar+64] = pa1.y;
        As[ac+2][ar+64] = pa1.z; As[ac+3][ar+64] = pa1.w;
        Ws[ac+0][ar]    = pw.x;  Ws[ac+1][ar]    = pw.y;
        Ws[ac+2][ar]    = pw.z;  Ws[ac+3][ar]    = pw.w;
        __syncthreads();

        if (t + 1 < nT) {
            const int off = (t + 1) * BK;
            pa0 = *(const float4*)(Ap0 + off);
            pa1 = *(const float4*)(Ap1 + off);
            pw  = *(const float4*)(Wp  + off);
            if (ADD2) {
                float4 q0 = *(const float4*)(A2p0 + off);
                float4 q1 = *(const float4*)(A2p1 + off);
                pa0.x += q0.x; pa0.y += q0.y; pa0.z += q0.z; pa0.w += q0.w;
                pa1.x += q1.x; pa1.y += q1.y; pa1.z += q1.z; pa1.w += q1.w;
            }
        }

        #pragma unroll
        for (int k = 0; k < BK; ++k) {
            float a[8], w[4];
            #pragma unroll
            for (int i = 0; i < 8; i++) a[i] = As[k][ty * 8 + i];
            #pragma unroll
            for (int j = 0; j < 4; j++) w[j] = Ws[k][tx * 4 + j];
            #pragma unroll
            for (int i = 0; i < 8; i++)
                #pragma unroll
                for (int j = 0; j < 4; j++) acc[i][j] += a[i] * w[j];
        }
        __syncthreads();
    }

    const float b0 = bias[n0 + tx*4 + 0];
    const float b1 = bias[n0 + tx*4 + 1];
    const float b2 = bias[n0 + tx*4 + 2];
    const float b3 = bias[n0 + tx*4 + 3];
    #pragma unroll
    for (int i = 0; i < 8; i++) {
        float4 o;
        o.x = acc[i][0] + b0; o.y = acc[i][1] + b1;
        o.z = acc[i][2] + b2; o.w = acc[i][3] + b3;
        if (RELU) {
            o.x = fmaxf(o.x, 0.f); o.y = fmaxf(o.y, 0.f);
            o.z = fmaxf(o.z, 0.f); o.w = fmaxf(o.w, 0.f);
        }
        *(float4*)(C + (size_t)(m0 + ty*8 + i) * Dout + n0 + tx*4) = o;
    }
}

// ---------------- fused attention: one CTA per (set, head) ----------------
#define ATTN_SMEM ((L_LEN*HD_DIM + M_BOX*HD_DIM + L_LEN*M_BOX) * 4 + L_LEN * 4)

__global__ __launch_bounds__(256)
void attn_kernel(const float* __restrict__ qbuf, const float* __restrict__ kbuf,
                 const float* __restrict__ vbuf, const int* __restrict__ vinds,
                 const int* __restrict__ vcoords, const int* __restrict__ bcoords,
                 float* __restrict__ ctxbuf)
{
    extern __shared__ float smf[];
    float* qs = smf;
    float* vs = qs + L_LEN * HD_DIM;
    float* sc = vs + M_BOX * HD_DIM;
    int*   qb = (int*)(sc + L_LEN * M_BOX);

    const int s = blockIdx.x;
    const int h = blockIdx.y;
    const int t = threadIdx.x;

    float kr[HD_DIM];
    {
        const float4* kp = (const float4*)(kbuf + (size_t)t * D_DIM + h * HD_DIM);
        const float4* vp = (const float4*)(vbuf + (size_t)t * D_DIM + h * HD_DIM);
        #pragma unroll
        for (int i = 0; i < 6; i++) {
            float4 f = kp[i];
            kr[4*i+0] = f.x; kr[4*i+1] = f.y; kr[4*i+2] = f.z; kr[4*i+3] = f.w;
            float4 g = vp[i];
            vs[t*HD_DIM + 4*i + 0] = g.x; vs[t*HD_DIM + 4*i + 1] = g.y;
            vs[t*HD_DIM + 4*i + 2] = g.z; vs[t*HD_DIM + 4*i + 3] = g.w;
        }
    }
    const int bb = bcoords[t * 4];

    if (t < L_LEN) qb[t] = vcoords[(size_t)vinds[s * L_LEN + t] * 4];
    for (int i = t; i < L_LEN * HD_DIM; i += 256) {
        int l = i / HD_DIM, dd = i % HD_DIM;
        qs[i] = qbuf[(size_t)vinds[s * L_LEN + l] * D_DIM + h * HD_DIM + dd];
    }
    __syncthreads();

    const float scale = 0.20412414523193154f;
    #pragma unroll 2
    for (int l = 0; l < L_LEN; l++) {
        const float* qr = qs + l * HD_DIM;
        float dot = 0.f;
        #pragma unroll
        for (int j = 0; j < HD_DIM; j++) dot += qr[j] * kr[j];
        sc[l * M_BOX + t] = (qb[l] != bb) ? -CUDART_INF_F : dot * scale;
    }
    __syncthreads();

    const int w = t >> 5, lane = t & 31;
    for (int l = w; l < L_LEN; l += 8) {
        float* row = sc + l * M_BOX;
        float e[8];
        float mx = -CUDART_INF_F;
        #pragma unroll
        for (int i = 0; i < 8; i++) { e[i] = row[lane + 32*i]; mx = fmaxf(mx, e[i]); }
        #pragma unroll
        for (int o = 16; o > 0; o >>= 1) mx = fmaxf(mx, __shfl_xor_sync(0xffffffffu, mx, o));
        float sum = 0.f;
        if (mx > -CUDART_INF_F) {
            #pragma unroll
            for (int i = 0; i < 8; i++) { e[i] = __expf(e[i] - mx); sum += e[i]; }
        } else {
            #pragma unroll
            for (int i = 0; i < 8; i++) e[i] = 0.f;
        }
        #pragma unroll
        for (int o = 16; o > 0; o >>= 1) sum += __shfl_xor_sync(0xffffffffu, sum, o);
        const float inv = sum > 0.f ? 1.0f / sum : 0.f;
        #pragma unroll
        for (int i = 0; i < 8; i++) row[lane + 32*i] = e[i] * inv;
    }
    __syncthreads();

    if (lane < HD_DIM) {
        const float* s0 = sc + (w +  0) * M_BOX;
        const float* s1 = sc + (w +  8) * M_BOX;
        const float* s2 = sc + (w + 16) * M_BOX;
        const float* s3 = sc + (w + 24) * M_BOX;
        const bool has5 = (w < L_LEN - 32);
        const float* s4 = has5 ? (sc + (w + 32) * M_BOX) : s0;
        float a0 = 0.f, a1 = 0.f, a2 = 0.f, a3 = 0.f, a4 = 0.f;
        #pragma unroll 2
        for (int m = 0; m < M_BOX; m++) {
            const float vv = vs[m * HD_DIM + lane];
            a0 += s0[m] * vv;
            a1 += s1[m] * vv;
            a2 += s2[m] * vv;
            a3 += s3[m] * vv;
            if (has5) a4 += s4[m] * vv;
        }
        const size_t base = (size_t)s * L_LEN;
        const int    off  = h * HD_DIM + lane;
        ctxbuf[(base + w +  0) * D_DIM + off] = a0;
        ctxbuf[(base + w +  8) * D_DIM + off] = a1;
        ctxbuf[(base + w + 16) * D_DIM + off] = a2;
        ctxbuf[(base + w + 24) * D_DIM + off] = a3;
        if (has5) ctxbuf[(base + w + 32) * D_DIM + off] = a4;
    }
}

// ---------------- first-occurrence scatter index ----------------
__global__ void init_fp_kernel(int* __restrict__ fp)
{
    int i = blockIdx.x * blockDim.x + threadIdx.x;
    if (i < N_PTS) fp[i] = 0x7FFFFFFF;
}

__global__ void fill_fp_kernel(const int* __restrict__ vinds, int* __restrict__ fp)
{
    int p = blockIdx.x * blockDim.x + threadIdx.x;
    if (p < S_SETS * L_LEN) {
        int n = vinds[p];
        if (n >= 0 && n < N_PTS) atomicMin(&fp[n], p);
    }
}

// ---------------- residual + layernorm (warp per row) ----------------
template<bool GATHER>
__global__ __launch_bounds__(256)
void ln_kernel(const float* __restrict__ a, const float* __restrict__ b,
               const int* __restrict__ fp, const float* __restrict__ gamma,
               const float* __restrict__ beta, float* __restrict__ outp)
{
    const int row  = (blockIdx.x * 256 + threadIdx.x) >> 5;
    const int lane = threadIdx.x & 31;
    if (row >= N_PTS) return;

    const float* arow = a + (size_t)row * D_DIM;
    const float* brow;
    if (GATHER) {
        int p = fp[row];
        if (p < 0 || p >= N_PTS) p = row;
        brow = b + (size_t)p * D_DIM;
    } else {
        brow = b + (size_t)row * D_DIM;
    }

    float v[6];
    float s = 0.f;
    #pragma unroll
    for (int i = 0; i < 6; i++) {
        const int idx = lane + 32 * i;
        v[i] = arow[idx] + brow[idx];
        s += v[i];
    }
    #pragma unroll
    for (int o = 16; o > 0; o >>= 1) s += __shfl_xor_sync(0xffffffffu, s, o);
    const float mean = s * (1.0f / D_DIM);

    float q = 0.f;
    #pragma unroll
    for (int i = 0; i < 6; i++) { const float d = v[i] - mean; q += d * d; }
    #pragma unroll
    for (int o = 16; o > 0; o >>= 1) q += __shfl_xor_sync(0xffffffffu, q, o);
    const float inv = rsqrtf(q * (1.0f / D_DIM) + 1e-5f);

    float* orow = outp + (size_t)row * D_DIM;
    #pragma unroll
    for (int i = 0; i < 6; i++) {
        const int idx = lane + 32 * i;
        orow[idx] = (v[i] - mean) * inv * gamma[idx] + beta[idx];
    }
}

// ---------------- elementwise add then feed GEMM A (src + pos) ----------------
__global__ void add_kernel(const float* __restrict__ a, const float* __restrict__ b,
                           float* __restrict__ c, int n4)
{
    int i = blockIdx.x * blockDim.x + threadIdx.x;
    if (i >= n4) return;
    float4 x = ((const float4*)a)[i];
    float4 y = ((const float4*)b)[i];
    x.x += y.x; x.y += y.y; x.z += y.z; x.w += y.w;
    ((float4*)c)[i] = x;
}

// ---------------- launch ----------------
extern "C" void kernel_launch(void* const* d_in, const int* in_sizes, int n_in,
                              void* d_out, int out_size)
{
    const float* src     = (const float*)d_in[0];
    const float* pos     = (const float*)d_in[1];
    const float* boxf    = (const float*)d_in[2];
    const float* boxp    = (const float*)d_in[3];
    const int*   vcoords = (const int*)  d_in[4];
    const int*   bcoords = (const int*)  d_in[5];
    const int*   vinds   = (const int*)  d_in[6];
    const float* Wq = (const float*)d_in[7];  const float* bq  = (const float*)d_in[8];
    const float* Wk = (const float*)d_in[9];  const float* bk  = (const float*)d_in[10];
    const float* Wv = (const float*)d_in[11]; const float* bv  = (const float*)d_in[12];
    const float* Wo = (const float*)d_in[13]; const float* bo  = (const float*)d_in[14];
    const float* W1 = (const float*)d_in[15]; const float* b1  = (const float*)d_in[16];
    const float* W2 = (const float*)d_in[17]; const float* b2  = (const float*)d_in[18];
    const float* g1 = (const float*)d_in[19]; const float* be1 = (const float*)d_in[20];
    const float* g2 = (const float*)d_in[21]; const float* be2 = (const float*)d_in[22];
    float* out = (float*)d_out;

    float *qb, *ctxb, *projb, *xb, *yb, *hb, *kb, *vb;
    int* fpb;
    cudaGetSymbolAddress((void**)&qb,    g_q);
    cudaGetSymbolAddress((void**)&ctxb,  g_ctx);
    cudaGetSymbolAddress((void**)&projb, g_proj);
    cudaGetSymbolAddress((void**)&xb,    g_x);
    cudaGetSymbolAddress((void**)&yb,    g_y);
    cudaGetSymbolAddress((void**)&hb,    g_h);
    cudaGetSymbolAddress((void**)&kb,    g_k);
    cudaGetSymbolAddress((void**)&vb,    g_v);
    cudaGetSymbolAddress((void**)&fpb,   g_fp);

    cudaFuncSetAttribute(attn_kernel, cudaFuncAttributeMaxDynamicSharedMemorySize, ATTN_SMEM);

    const int MB = N_PTS / TBM;   // 720

    // qin = src + pos (reuse g_y as staging; overwritten later by FFN2)
    {
        const int n4 = N_PTS * D_DIM / 4;
        add_kernel<<<(n4 + 255)/256, 256>>>(src, pos, yb, n4);
    }

    // K = (box_feature + box_pos) @ Wk^T + bk ; V = box_feature @ Wv^T + bv (tiny, SIMT)
    gemm_kernel<false, true ><<<dim3(D_DIM/BN, M_BOX/BM), 256>>>(boxf, boxp,    Wk, bk, kb, BD_DIM, D_DIM);
    gemm_kernel<false, false><<<dim3(D_DIM/BN, M_BOX/BM), 256>>>(boxf, nullptr, Wv, bv, vb, BD_DIM, D_DIM);

    // Q = (src + pos) @ Wq^T + bq  (tensor cores, tf32)
    wmma_gemm<false><<<dim3(D_DIM/TBN, MB), 256, WMMA_SMEM>>>(yb, Wq, bq, qb, D_DIM, D_DIM);

    // fused masked attention
    attn_kernel<<<dim3(S_SETS, H_HEADS), 256, ATTN_SMEM>>>(qb, kb, vb, vinds, vcoords, bcoords, ctxb);

    // O projection
    wmma_gemm<false><<<dim3(D_DIM/TBN, MB), 256, WMMA_SMEM>>>(ctxb, Wo, bo, projb, D_DIM, D_DIM);

    // first-occurrence scatter index
    init_fp_kernel<<<N_PTS / 256, 256>>>(fpb);
    fill_fp_kernel<<<(S_SETS * L_LEN) / 256, 256>>>(vinds, fpb);

    // x = LN(src + proj[first_pos])
    ln_kernel<true ><<<N_PTS / 8, 256>>>(src, projb, fpb, g1, be1, xb);

    // FFN
    wmma_gemm<true ><<<dim3(FF_DIM/TBN, MB), 256, WMMA_SMEM>>>(xb, W1, b1, hb, D_DIM,  FF_DIM);
    wmma_gemm<false><<<dim3(D_DIM/TBN, MB), 256, WMMA_SMEM>>>(hb, W2, b2, yb, FF_DIM, D_DIM);

    // out = LN(x + ffn)
    ln_kernel<false><<<N_PTS / 8, 256>>>(xb, yb, nullptr, g2, be2, out);
}

// round 4
// speedup vs baseline: 2.2897x; 2.2897x over previous
#include <cuda_runtime.h>
#include <cuda_fp16.h>
#include <math_constants.h>
#include <cstdint>

#define N_PTS   92160
#define D_DIM   192
#define BD_DIM  256
#define H_HEADS 8
#define FF_DIM  768
#define S_SETS  2560
#define L_LEN   36
#define M_BOX   256
#define HD_DIM  24

// ---------------- scratch (static device globals; no allocation) ----------------
__device__ float g_q[N_PTS * D_DIM];
__device__ float g_proj[N_PTS * D_DIM];
__device__ float g_x[N_PTS * D_DIM];
__device__ float g_y[N_PTS * D_DIM];
__device__ float g_k[M_BOX * D_DIM];
__device__ float g_v[M_BOX * D_DIM];
__device__ int   g_fp[N_PTS];

__device__ __half g_qinh[N_PTS * D_DIM];
__device__ __half g_ctxh[N_PTS * D_DIM];
__device__ __half g_xh[N_PTS * D_DIM];
__device__ __half g_hh[(size_t)N_PTS * FF_DIM];
// weight halves: wq @0 (36864), wo @36864, w1 @73728 (147456), w2 @221184 (147456)
#define WOFF_Q 0
#define WOFF_O 36864
#define WOFF_1 73728
#define WOFF_2 221184
__device__ __half g_wh[368640];

// ================= fp16 mma.sync GEMM: C = A @ W^T + bias =================
// A: (Mrows, K) half row-major, W: (Dout, K) half row-major.
// CTA tile 128 x 64, BK = 32, 256 threads = 8 warps (4m x 2n), warp tile 32 x 32.
// smem rows padded to 40 halves -> fragment lds.b32 pattern is bank-conflict-free.
#define HPAD 40

__device__ __forceinline__ void mma16816(float* d, const uint32_t* a, const uint32_t* b) {
    asm volatile(
        "mma.sync.aligned.m16n8k16.row.col.f32.f16.f16.f32 "
        "{%0,%1,%2,%3}, {%4,%5,%6,%7}, {%8,%9}, {%0,%1,%2,%3};\n"
        : "+f"(d[0]), "+f"(d[1]), "+f"(d[2]), "+f"(d[3])
        : "r"(a[0]), "r"(a[1]), "r"(a[2]), "r"(a[3]), "r"(b[0]), "r"(b[1]));
}

template<bool RELU, bool OUTH>
__global__ __launch_bounds__(256)
void hgemm(const __half* __restrict__ A, const __half* __restrict__ W,
           const float* __restrict__ bias, float* __restrict__ C,
           __half* __restrict__ Ch, int K, int Dout)
{
    __shared__ __half As[128 * HPAD];
    __shared__ __half Ws[64 * HPAD];

    const int tid  = threadIdx.x;
    const int lane = tid & 31;
    const int wid  = tid >> 5;
    const int wm   = wid & 3;          // 0..3 -> 32-row band
    const int wn   = wid >> 2;         // 0..1 -> 32-col band
    const int m0   = blockIdx.y * 128;
    const int n0   = blockIdx.x * 64;
    const int lr   = lane >> 2;        // 0..7
    const int lc2  = (lane & 3) * 2;   // 0,2,4,6

    // global->smem mapping (16B chunks)
    const int rA0 = tid >> 2, cA = tid & 3;          // e=0 rows 0..63, e=1 rows 64..127
    const __half* ApA0 = A + (size_t)(m0 + rA0)      * K + cA * 8;
    const __half* ApA1 = A + (size_t)(m0 + rA0 + 64) * K + cA * 8;
    const __half* WpW  = W + (size_t)(n0 + rA0)      * K + cA * 8;   // rows 0..63
    const int sA0 = rA0 * HPAD + cA * 8;
    const int sA1 = (rA0 + 64) * HPAD + cA * 8;
    const int sW  = rA0 * HPAD + cA * 8;

    const int nT = K >> 5;

    uint4 pa0 = *(const uint4*)ApA0;
    uint4 pa1 = *(const uint4*)ApA1;
    uint4 pw  = *(const uint4*)WpW;

    float acc[2][4][4];
    #pragma unroll
    for (int i = 0; i < 2; i++)
        #pragma unroll
        for (int j = 0; j < 4; j++)
            #pragma unroll
            for (int e = 0; e < 4; e++) acc[i][j][e] = 0.f;

    for (int t = 0; t < nT; ++t) {
        *(uint4*)(As + sA0) = pa0;
        *(uint4*)(As + sA1) = pa1;
        *(uint4*)(Ws + sW)  = pw;
        __syncthreads();

        if (t + 1 < nT) {
            const int off = (t + 1) * 32;
            pa0 = *(const uint4*)(ApA0 + off);
            pa1 = *(const uint4*)(ApA1 + off);
            pw  = *(const uint4*)(WpW  + off);
        }

        #pragma unroll
        for (int ks = 0; ks < 32; ks += 16) {
            uint32_t af[2][4], bf[4][2];
            #pragma unroll
            for (int i = 0; i < 2; i++) {
                const int base = (wm * 32 + i * 16 + lr) * HPAD + ks + lc2;
                af[i][0] = *(const uint32_t*)(As + base);
                af[i][1] = *(const uint32_t*)(As + base + 8 * HPAD);
                af[i][2] = *(const uint32_t*)(As + base + 8);
                af[i][3] = *(const uint32_t*)(As + base + 8 * HPAD + 8);
            }
            #pragma unroll
            for (int j = 0; j < 4; j++) {
                const int base = (wn * 32 + j * 8 + lr) * HPAD + ks + lc2;
                bf[j][0] = *(const uint32_t*)(Ws + base);
                bf[j][1] = *(const uint32_t*)(Ws + base + 8);
            }
            #pragma unroll
            for (int i = 0; i < 2; i++)
                #pragma unroll
                for (int j = 0; j < 4; j++)
                    mma16816(acc[i][j], af[i], bf[j]);
        }
        __syncthreads();
    }

    // epilogue: direct stores, bias preloaded per thread
    float2 bx[4];
    #pragma unroll
    for (int j = 0; j < 4; j++) {
        const int cj = n0 + wn * 32 + j * 8 + lc2;
        bx[j] = *(const float2*)(bias + cj);
    }
    #pragma unroll
    for (int i = 0; i < 2; i++) {
        const int r0 = m0 + wm * 32 + i * 16 + lr;
        #pragma unroll
        for (int j = 0; j < 4; j++) {
            const int cj = n0 + wn * 32 + j * 8 + lc2;
            float v0 = acc[i][j][0] + bx[j].x;
            float v1 = acc[i][j][1] + bx[j].y;
            float v2 = acc[i][j][2] + bx[j].x;
            float v3 = acc[i][j][3] + bx[j].y;
            if (RELU) {
                v0 = fmaxf(v0, 0.f); v1 = fmaxf(v1, 0.f);
                v2 = fmaxf(v2, 0.f); v3 = fmaxf(v3, 0.f);
            }
            if (OUTH) {
                *(__half2*)(Ch + (size_t)r0       * Dout + cj) = __floats2half2_rn(v0, v1);
                *(__half2*)(Ch + (size_t)(r0 + 8) * Dout + cj) = __floats2half2_rn(v2, v3);
            } else {
                *(float2*)(C + (size_t)r0       * Dout + cj) = make_float2(v0, v1);
                *(float2*)(C + (size_t)(r0 + 8) * Dout + cj) = make_float2(v2, v3);
            }
        }
    }
}

// ---------------- small SIMT GEMM for K/V projections ----------------
#define BM 128
#define BN 64
#define BK 16

template<bool RELU, bool ADD2>
__global__ __launch_bounds__(256, 2)
void gemm_kernel(const float* __restrict__ A, const float* __restrict__ A2,
                 const float* __restrict__ W, const float* __restrict__ bias,
                 float* __restrict__ C, int K, int Dout)
{
    __shared__ float As[BK][BM + 4];
    __shared__ float Ws[BK][BN + 4];

    const int tid = threadIdx.x;
    const int tx = tid & 15;
    const int ty = tid >> 4;
    const int m0 = blockIdx.y * BM;
    const int n0 = blockIdx.x * BN;

    const int ar = tid >> 2;
    const int ac = (tid & 3) << 2;

    const float* Ap0  = A  + (size_t)(m0 + ar)      * K + ac;
    const float* Ap1  = A  + (size_t)(m0 + ar + 64) * K + ac;
    const float* A2p0 = ADD2 ? (A2 + (size_t)(m0 + ar)      * K + ac) : nullptr;
    const float* A2p1 = ADD2 ? (A2 + (size_t)(m0 + ar + 64) * K + ac) : nullptr;
    const float* Wp   = W  + (size_t)(n0 + ar)      * K + ac;

    const int nT = K / BK;

    float4 pa0 = *(const float4*)(Ap0);
    float4 pa1 = *(const float4*)(Ap1);
    float4 pw  = *(const float4*)(Wp);
    if (ADD2) {
        float4 q0 = *(const float4*)(A2p0);
        float4 q1 = *(const float4*)(A2p1);
        pa0.x += q0.x; pa0.y += q0.y; pa0.z += q0.z; pa0.w += q0.w;
        pa1.x += q1.x; pa1.y += q1.y; pa1.z += q1.z; pa1.w += q1.w;
    }

    float acc[8][4];
    #pragma unroll
    for (int i = 0; i < 8; i++)
        #pragma unroll
        for (int j = 0; j < 4; j++) acc[i][j] = 0.f;

    for (int t = 0; t < nT; ++t) {
        As[ac+0][ar]    = pa0.x; As[ac+1][ar]    = pa0.y;
        As[ac+2][ar]    = pa0.z; As[ac+3][ar]    = pa0.w;
        As[ac+0][ar+64] = pa1.x; As[ac+1][ar+64] = pa1.y;
        As[ac+2][ar+64] = pa1.z; As[ac+3][ar+64] = pa1.w;
        Ws[ac+0][ar]    = pw.x;  Ws[ac+1][ar]    = pw.y;
        Ws[ac+2][ar]    = pw.z;  Ws[ac+3][ar]    = pw.w;
        __syncthreads();

        if (t + 1 < nT) {
            const int off = (t + 1) * BK;
            pa0 = *(const float4*)(Ap0 + off);
            pa1 = *(const float4*)(Ap1 + off);
            pw  = *(const float4*)(Wp  + off);
            if (ADD2) {
                float4 q0 = *(const float4*)(A2p0 + off);
                float4 q1 = *(const float4*)(A2p1 + off);
                pa0.x += q0.x; pa0.y += q0.y; pa0.z += q0.z; pa0.w += q0.w;
                pa1.x += q1.x; pa1.y += q1.y; pa1.z += q1.z; pa1.w += q1.w;
            }
        }

        #pragma unroll
        for (int k = 0; k < BK; ++k) {
            float a[8], w[4];
            #pragma unroll
            for (int i = 0; i < 8; i++) a[i] = As[k][ty * 8 + i];
            #pragma unroll
            for (int j = 0; j < 4; j++) w[j] = Ws[k][tx * 4 + j];
            #pragma unroll
            for (int i = 0; i < 8; i++)
                #pragma unroll
                for (int j = 0; j < 4; j++) acc[i][j] += a[i] * w[j];
        }
        __syncthreads();
    }

    const float b0 = bias[n0 + tx*4 + 0];
    const float b1 = bias[n0 + tx*4 + 1];
    const float b2 = bias[n0 + tx*4 + 2];
    const float b3 = bias[n0 + tx*4 + 3];
    #pragma unroll
    for (int i = 0; i < 8; i++) {
        float4 o;
        o.x = acc[i][0] + b0; o.y = acc[i][1] + b1;
        o.z = acc[i][2] + b2; o.w = acc[i][3] + b3;
        if (RELU) {
            o.x = fmaxf(o.x, 0.f); o.y = fmaxf(o.y, 0.f);
            o.z = fmaxf(o.z, 0.f); o.w = fmaxf(o.w, 0.f);
        }
        *(float4*)(C + (size_t)(m0 + ty*8 + i) * Dout + n0 + tx*4) = o;
    }
}

// ---------------- fused attention: one CTA per (set, head), writes half ctx ----------------
#define ATTN_SMEM ((L_LEN*HD_DIM + M_BOX*HD_DIM + L_LEN*M_BOX) * 4 + L_LEN * 4)

__global__ __launch_bounds__(256)
void attn_kernel(const float* __restrict__ qbuf, const float* __restrict__ kbuf,
                 const float* __restrict__ vbuf, const int* __restrict__ vinds,
                 const int* __restrict__ vcoords, const int* __restrict__ bcoords,
                 __half* __restrict__ ctxh)
{
    extern __shared__ float smf[];
    float* qs = smf;
    float* vs = qs + L_LEN * HD_DIM;
    float* sc = vs + M_BOX * HD_DIM;
    int*   qb = (int*)(sc + L_LEN * M_BOX);

    const int s = blockIdx.x;
    const int h = blockIdx.y;
    const int t = threadIdx.x;

    float kr[HD_DIM];
    {
        const float4* kp = (const float4*)(kbuf + (size_t)t * D_DIM + h * HD_DIM);
        const float4* vp = (const float4*)(vbuf + (size_t)t * D_DIM + h * HD_DIM);
        #pragma unroll
        for (int i = 0; i < 6; i++) {
            float4 f = kp[i];
            kr[4*i+0] = f.x; kr[4*i+1] = f.y; kr[4*i+2] = f.z; kr[4*i+3] = f.w;
            float4 g = vp[i];
            vs[t*HD_DIM + 4*i + 0] = g.x; vs[t*HD_DIM + 4*i + 1] = g.y;
            vs[t*HD_DIM + 4*i + 2] = g.z; vs[t*HD_DIM + 4*i + 3] = g.w;
        }
    }
    const int bb = bcoords[t * 4];

    if (t < L_LEN) qb[t] = vcoords[(size_t)vinds[s * L_LEN + t] * 4];
    for (int i = t; i < L_LEN * HD_DIM; i += 256) {
        int l = i / HD_DIM, dd = i % HD_DIM;
        qs[i] = qbuf[(size_t)vinds[s * L_LEN + l] * D_DIM + h * HD_DIM + dd];
    }
    __syncthreads();

    const float scale = 0.20412414523193154f;
    #pragma unroll 2
    for (int l = 0; l < L_LEN; l++) {
        const float* qr = qs + l * HD_DIM;
        float dot = 0.f;
        #pragma unroll
        for (int j = 0; j < HD_DIM; j++) dot += qr[j] * kr[j];
        sc[l * M_BOX + t] = (qb[l] != bb) ? -CUDART_INF_F : dot * scale;
    }
    __syncthreads();

    const int w = t >> 5, lane = t & 31;
    for (int l = w; l < L_LEN; l += 8) {
        float* row = sc + l * M_BOX;
        float e[8];
        float mx = -CUDART_INF_F;
        #pragma unroll
        for (int i = 0; i < 8; i++) { e[i] = row[lane + 32*i]; mx = fmaxf(mx, e[i]); }
        #pragma unroll
        for (int o = 16; o > 0; o >>= 1) mx = fmaxf(mx, __shfl_xor_sync(0xffffffffu, mx, o));
        float sum = 0.f;
        if (mx > -CUDART_INF_F) {
            #pragma unroll
            for (int i = 0; i < 8; i++) { e[i] = __expf(e[i] - mx); sum += e[i]; }
        } else {
            #pragma unroll
            for (int i = 0; i < 8; i++) e[i] = 0.f;
        }
        #pragma unroll
        for (int o = 16; o > 0; o >>= 1) sum += __shfl_xor_sync(0xffffffffu, sum, o);
        const float inv = sum > 0.f ? 1.0f / sum : 0.f;
        #pragma unroll
        for (int i = 0; i < 8; i++) row[lane + 32*i] = e[i] * inv;
    }
    __syncthreads();

    if (lane < HD_DIM) {
        const float* s0 = sc + (w +  0) * M_BOX;
        const float* s1 = sc + (w +  8) * M_BOX;
        const float* s2 = sc + (w + 16) * M_BOX;
        const float* s3 = sc + (w + 24) * M_BOX;
        const bool has5 = (w < L_LEN - 32);
        const float* s4 = has5 ? (sc + (w + 32) * M_BOX) : s0;
        float a0 = 0.f, a1 = 0.f, a2 = 0.f, a3 = 0.f, a4 = 0.f;
        #pragma unroll 2
        for (int m = 0; m < M_BOX; m++) {
            const float vv = vs[m * HD_DIM + lane];
            a0 += s0[m] * vv;
            a1 += s1[m] * vv;
            a2 += s2[m] * vv;
            a3 += s3[m] * vv;
            if (has5) a4 += s4[m] * vv;
        }
        const size_t base = (size_t)s * L_LEN;
        const int    off  = h * HD_DIM + lane;
        ctxh[(base + w +  0) * D_DIM + off] = __float2half(a0);
        ctxh[(base + w +  8) * D_DIM + off] = __float2half(a1);
        ctxh[(base + w + 16) * D_DIM + off] = __float2half(a2);
        ctxh[(base + w + 24) * D_DIM + off] = __float2half(a3);
        if (has5) ctxh[(base + w + 32) * D_DIM + off] = __float2half(a4);
    }
}

// ---------------- first-occurrence scatter index ----------------
__global__ void init_fp_kernel(int* __restrict__ fp)
{
    int i = blockIdx.x * blockDim.x + threadIdx.x;
    if (i < N_PTS) fp[i] = 0x7FFFFFFF;
}

__global__ void fill_fp_kernel(const int* __restrict__ vinds, int* __restrict__ fp)
{
    int p = blockIdx.x * blockDim.x + threadIdx.x;
    if (p < S_SETS * L_LEN) {
        int n = vinds[p];
        if (n >= 0 && n < N_PTS) atomicMin(&fp[n], p);
    }
}

// ---------------- residual + layernorm (warp per row) ----------------
template<bool GATHER, bool OUTH>
__global__ __launch_bounds__(256)
void ln_kernel(const float* __restrict__ a, const float* __restrict__ b,
               const int* __restrict__ fp, const float* __restrict__ gamma,
               const float* __restrict__ beta, float* __restrict__ outp,
               __half* __restrict__ oh)
{
    const int row  = (blockIdx.x * 256 + threadIdx.x) >> 5;
    const int lane = threadIdx.x & 31;
    if (row >= N_PTS) return;

    const float* arow = a + (size_t)row * D_DIM;
    const float* brow;
    if (GATHER) {
        int p = fp[row];
        if (p < 0 || p >= N_PTS) p = row;
        brow = b + (size_t)p * D_DIM;
    } else {
        brow = b + (size_t)row * D_DIM;
    }

    float v[6];
    float s = 0.f;
    #pragma unroll
    for (int i = 0; i < 6; i++) {
        const int idx = lane + 32 * i;
        v[i] = arow[idx] + brow[idx];
        s += v[i];
    }
    #pragma unroll
    for (int o = 16; o > 0; o >>= 1) s += __shfl_xor_sync(0xffffffffu, s, o);
    const float mean = s * (1.0f / D_DIM);

    float q = 0.f;
    #pragma unroll
    for (int i = 0; i < 6; i++) { const float d = v[i] - mean; q += d * d; }
    #pragma unroll
    for (int o = 16; o > 0; o >>= 1) q += __shfl_xor_sync(0xffffffffu, q, o);
    const float inv = rsqrtf(q * (1.0f / D_DIM) + 1e-5f);

    float* orow = outp + (size_t)row * D_DIM;
    #pragma unroll
    for (int i = 0; i < 6; i++) {
        const int idx = lane + 32 * i;
        const float val = (v[i] - mean) * inv * gamma[idx] + beta[idx];
        orow[idx] = val;
        if (OUTH) oh[(size_t)row * D_DIM + idx] = __float2half(val);
    }
}

// ---------------- conversion kernels ----------------
__global__ void add_half_kernel(const float* __restrict__ a, const float* __restrict__ b,
                                __half* __restrict__ c, int n4)
{
    int i = blockIdx.x * blockDim.x + threadIdx.x;
    if (i >= n4) return;
    float4 x = ((const float4*)a)[i];
    float4 y = ((const float4*)b)[i];
    ((__half2*)c)[2*i]   = __floats2half2_rn(x.x + y.x, x.y + y.y);
    ((__half2*)c)[2*i+1] = __floats2half2_rn(x.z + y.z, x.w + y.w);
}

__global__ void cvt_half_kernel(const float* __restrict__ a, __half* __restrict__ c, int n4)
{
    int i = blockIdx.x * blockDim.x + threadIdx.x;
    if (i >= n4) return;
    float4 x = ((const float4*)a)[i];
    ((__half2*)c)[2*i]   = __floats2half2_rn(x.x, x.y);
    ((__half2*)c)[2*i+1] = __floats2half2_rn(x.z, x.w);
}

// ---------------- launch ----------------
extern "C" void kernel_launch(void* const* d_in, const int* in_sizes, int n_in,
                              void* d_out, int out_size)
{
    const float* src     = (const float*)d_in[0];
    const float* pos     = (const float*)d_in[1];
    const float* boxf    = (const float*)d_in[2];
    const float* boxp    = (const float*)d_in[3];
    const int*   vcoords = (const int*)  d_in[4];
    const int*   bcoords = (const int*)  d_in[5];
    const int*   vinds   = (const int*)  d_in[6];
    const float* Wq = (const float*)d_in[7];  const float* bq  = (const float*)d_in[8];
    const float* Wk = (const float*)d_in[9];  const float* bk  = (const float*)d_in[10];
    const float* Wv = (const float*)d_in[11]; const float* bv  = (const float*)d_in[12];
    const float* Wo = (const float*)d_in[13]; const float* bo  = (const float*)d_in[14];
    const float* W1 = (const float*)d_in[15]; const float* b1  = (const float*)d_in[16];
    const float* W2 = (const float*)d_in[17]; const float* b2  = (const float*)d_in[18];
    const float* g1 = (const float*)d_in[19]; const float* be1 = (const float*)d_in[20];
    const float* g2 = (const float*)d_in[21]; const float* be2 = (const float*)d_in[22];
    float* out = (float*)d_out;

    float *qb, *projb, *xb, *yb, *kb, *vb;
    int* fpb;
    __half *qinh, *ctxh, *xh, *hh, *wh;
    cudaGetSymbolAddress((void**)&qb,    g_q);
    cudaGetSymbolAddress((void**)&projb, g_proj);
    cudaGetSymbolAddress((void**)&xb,    g_x);
    cudaGetSymbolAddress((void**)&yb,    g_y);
    cudaGetSymbolAddress((void**)&kb,    g_k);
    cudaGetSymbolAddress((void**)&vb,    g_v);
    cudaGetSymbolAddress((void**)&fpb,   g_fp);
    cudaGetSymbolAddress((void**)&qinh,  g_qinh);
    cudaGetSymbolAddress((void**)&ctxh,  g_ctxh);
    cudaGetSymbolAddress((void**)&xh,    g_xh);
    cudaGetSymbolAddress((void**)&hh,    g_hh);
    cudaGetSymbolAddress((void**)&wh,    g_wh);

    cudaFuncSetAttribute(attn_kernel, cudaFuncAttributeMaxDynamicSharedMemorySize, ATTN_SMEM);

    const int MB = N_PTS / 128;   // 720

    // conversions
    {
        const int n4 = N_PTS * D_DIM / 4;
        add_half_kernel<<<(n4 + 255)/256, 256>>>(src, pos, qinh, n4);
    }
    cvt_half_kernel<<<36864/4/256,  256>>>(Wq, wh + WOFF_Q, 36864/4);
    cvt_half_kernel<<<36864/4/256,  256>>>(Wo, wh + WOFF_O, 36864/4);
    cvt_half_kernel<<<147456/4/256, 256>>>(W1, wh + WOFF_1, 147456/4);
    cvt_half_kernel<<<147456/4/256, 256>>>(W2, wh + WOFF_2, 147456/4);

    // K/V projections (tiny, SIMT fp32)
    gemm_kernel<false, true ><<<dim3(D_DIM/BN, M_BOX/BM), 256>>>(boxf, boxp,    Wk, bk, kb, BD_DIM, D_DIM);
    gemm_kernel<false, false><<<dim3(D_DIM/BN, M_BOX/BM), 256>>>(boxf, nullptr, Wv, bv, vb, BD_DIM, D_DIM);

    // Q = (src + pos) @ Wq^T + bq (fp16 tensor cores)
    hgemm<false, false><<<dim3(D_DIM/64, MB), 256>>>(qinh, wh + WOFF_Q, bq, qb, nullptr, D_DIM, D_DIM);

    // fused masked attention (writes half ctx)
    attn_kernel<<<dim3(S_SETS, H_HEADS), 256, ATTN_SMEM>>>(qb, kb, vb, vinds, vcoords, bcoords, ctxh);

    // O projection
    hgemm<false, false><<<dim3(D_DIM/64, MB), 256>>>(ctxh, wh + WOFF_O, bo, projb, nullptr, D_DIM, D_DIM);

    // first-occurrence scatter index
    init_fp_kernel<<<N_PTS / 256, 256>>>(fpb);
    fill_fp_kernel<<<(S_SETS * L_LEN) / 256, 256>>>(vinds, fpb);

    // x = LN(src + proj[first_pos]) (+ half copy)
    ln_kernel<true, true><<<N_PTS / 8, 256>>>(src, projb, fpb, g1, be1, xb, xh);

    // FFN
    hgemm<true,  true ><<<dim3(FF_DIM/64, MB), 256>>>(xh, wh + WOFF_1, b1, nullptr, hh, D_DIM, FF_DIM);
    hgemm<false, false><<<dim3(D_DIM/64, MB), 256>>>(hh, wh + WOFF_2, b2, yb, nullptr, FF_DIM, D_DIM);

    // out = LN(x + ffn)
    ln_kernel<false, false><<<N_PTS / 8, 256>>>(xb, yb, nullptr, g2, be2, out, nullptr);
}